// round 1
// baseline (speedup 1.0000x reference)
#include <cuda_runtime.h>
#include <cuda_bf16.h>
#include <math.h>

// Problem: quantized softmax (SoftmaxBernoulli2), x:(2,16,2048,2048) int32 in [-128,127],
// LUT[q] = clip(round(exp((q-255)*input_scale)/exp_scale),0,255), q index = (x - rowmax) + 255,
// out = LUT[idx] / sum_row(LUT[idx])  as float32.
//
// Plan: kernel 1 builds the 256-entry table once (double precision, round-half-even to
// match jnp.round). Kernel 2: one 256-thread CTA per row of 2048; each thread owns 8
// elements in registers (2x int4 coalesced loads), block max-reduce, conflict-free
// replicated-LUT gather from smem, block sum-reduce (exact int), float4 stores.

#define ROW 2048
#define TPB 256
#define VPT 8  // values per thread

__device__ int g_table[256];

__global__ void build_table_kernel(const float* __restrict__ input_scale,
                                   const float* __restrict__ exp_scale) {
    int q = threadIdx.x;                         // 0..255 -> quant value q-255 in [-255,0]
    double is = (double)input_scale[0];
    double es = (double)exp_scale[0];
    double v = exp((double)(q - 255) * is) / es;
    double r = nearbyint(v);                     // round half to even, matches jnp.round
    r = fmin(fmax(r, 0.0), 255.0);
    g_table[q] = (int)r;
}

__global__ __launch_bounds__(TPB) void softmax_bernoulli2_kernel(
    const int* __restrict__ x, float* __restrict__ out) {
    // Replicated LUT: tab[idx*32 + lane] -> bank == lane, conflict-free gather.
    __shared__ int s_tab[256 * 32];
    __shared__ int s_red[TPB / 32];
    __shared__ int s_bcast;

    const int tid  = threadIdx.x;
    const int lane = tid & 31;
    const int warp = tid >> 5;

    // Fill replicated table: consecutive lanes -> same entry (broadcast load),
    // consecutive banks (conflict-free store). 32 iterations.
    #pragma unroll 4
    for (int i = tid; i < 256 * 32; i += TPB) {
        s_tab[i] = g_table[i >> 5];
    }

    // Load this row: thread t owns elements [t*8, t*8+8) via two int4 (coalesced 128B).
    const long long row = blockIdx.x;
    const int4* xp = reinterpret_cast<const int4*>(x + row * ROW) + tid * 2;
    int4 a = xp[0];
    int4 b = xp[1];
    int v[VPT] = {a.x, a.y, a.z, a.w, b.x, b.y, b.z, b.w};

    // ---- block max reduce ----
    int m = v[0];
    #pragma unroll
    for (int k = 1; k < VPT; k++) m = max(m, v[k]);
    #pragma unroll
    for (int o = 16; o > 0; o >>= 1) m = max(m, __shfl_xor_sync(0xFFFFFFFFu, m, o));
    if (lane == 0) s_red[warp] = m;
    __syncthreads();   // also fences the table fill
    if (warp == 0) {
        int mm = (lane < TPB / 32) ? s_red[lane] : (-0x7FFFFFFF - 1);
        #pragma unroll
        for (int o = 4; o > 0; o >>= 1) mm = max(mm, __shfl_xor_sync(0xFFFFFFFFu, mm, o));
        if (lane == 0) s_bcast = mm;
    }
    __syncthreads();
    const int xmax = s_bcast;

    // ---- gather exp_q from LUT, accumulate exact int sum ----
    int e[VPT];
    int sum = 0;
    #pragma unroll
    for (int k = 0; k < VPT; k++) {
        int idx = v[k] - xmax + 255;
        idx = min(max(idx, 0), 255);
        e[k] = s_tab[(idx << 5) + lane];
        sum += e[k];
    }

    // ---- block sum reduce ----
    #pragma unroll
    for (int o = 16; o > 0; o >>= 1) sum += __shfl_xor_sync(0xFFFFFFFFu, sum, o);
    if (lane == 0) s_red[warp] = sum;
    __syncthreads();
    if (warp == 0) {
        int ss = (lane < TPB / 32) ? s_red[lane] : 0;
        #pragma unroll
        for (int o = 4; o > 0; o >>= 1) ss += __shfl_xor_sync(0xFFFFFFFFu, ss, o);
        if (lane == 0) s_bcast = ss;
    }
    __syncthreads();
    const float inv = 1.0f / (float)s_bcast;

    // ---- write 8 floats via two float4 (coalesced) ----
    float4 o0, o1;
    o0.x = (float)e[0] * inv; o0.y = (float)e[1] * inv;
    o0.z = (float)e[2] * inv; o0.w = (float)e[3] * inv;
    o1.x = (float)e[4] * inv; o1.y = (float)e[5] * inv;
    o1.z = (float)e[6] * inv; o1.w = (float)e[7] * inv;
    float4* op = reinterpret_cast<float4*>(out + row * ROW) + tid * 2;
    op[0] = o0;
    op[1] = o1;
}

extern "C" void kernel_launch(void* const* d_in, const int* in_sizes, int n_in,
                              void* d_out, int out_size) {
    const int* x            = (const int*)d_in[0];
    const float* input_scale = (const float*)d_in[1];
    const float* exp_scale   = (const float*)d_in[2];
    float* out = (float*)d_out;

    const int n_elems = in_sizes[0];
    const int n_rows  = n_elems / ROW;   // 65536

    build_table_kernel<<<1, 256>>>(input_scale, exp_scale);
    softmax_bernoulli2_kernel<<<n_rows, TPB>>>(x, out);
}

// round 2
// speedup vs baseline: 1.6599x; 1.6599x over previous
#include <cuda_runtime.h>
#include <cuda_bf16.h>
#include <math.h>

// Quantized softmax (SoftmaxBernoulli2): x (N rows of 2048) int32 in [-128,127].
// LUT[q] = clip(round(exp((q-255)*is)/es),0,255); idx = x - rowmax + 255;
// out = LUT[idx] / sum_row(LUT[idx]) as fp32.
//
// R2: persistent CTAs (fill 32KB replicated LUT once, grid-stride over rows),
// cross-row int4 prefetch, single-barrier-per-reduction (all threads read the
// 8 warp partials). Target: DRAM-bound (~1 GiB traffic -> ~170us floor).

#define ROW   2048
#define TPB   256
#define VPT   8
#define NWARP (TPB / 32)

__device__ int g_table[256];

__global__ void build_table_kernel(const float* __restrict__ input_scale,
                                   const float* __restrict__ exp_scale) {
    int q = threadIdx.x;                     // table index 0..255 -> quant q-255
    double is = (double)input_scale[0];
    double es = (double)exp_scale[0];
    double v = exp((double)(q - 255) * is) / es;
    double r = nearbyint(v);                 // half-even, matches jnp.round
    r = fmin(fmax(r, 0.0), 255.0);
    g_table[q] = (int)r;
}

__global__ __launch_bounds__(TPB) void softmax_bernoulli2_kernel(
    const int* __restrict__ x, float* __restrict__ out, int n_rows) {
    // Replicated LUT: s_tab[idx*32 + lane] -> bank == lane, conflict-free gather.
    __shared__ int s_tab[256 * 32];
    __shared__ int s_max[NWARP];
    __shared__ int s_sum[NWARP];

    const int tid  = threadIdx.x;
    const int lane = tid & 31;
    const int warp = tid >> 5;

    // One-time fill: broadcast LDG, conflict-free STS. Amortized over ~70 rows.
    #pragma unroll 4
    for (int i = tid; i < 256 * 32; i += TPB) {
        s_tab[i] = g_table[i >> 5];
    }
    __syncthreads();

    const long long stride = gridDim.x;
    long long row = blockIdx.x;
    if (row >= n_rows) return;

    // Prefetch first row: thread t owns elements [t*8, t*8+8), two int4 (128B coalesced).
    int4 a = *(reinterpret_cast<const int4*>(x + row * ROW) + tid * 2);
    int4 b = *(reinterpret_cast<const int4*>(x + row * ROW) + tid * 2 + 1);

    for (; row < n_rows; row += stride) {
        int v[VPT] = {a.x, a.y, a.z, a.w, b.x, b.y, b.z, b.w};

        // Issue next row's loads NOW so they fly during the reductions.
        long long nrow = row + stride;
        if (nrow < n_rows) {
            const int4* np = reinterpret_cast<const int4*>(x + nrow * ROW) + tid * 2;
            a = np[0];
            b = np[1];
        }

        // ---- block max: warp shfl reduce, then all threads scan 8 partials ----
        int m = v[0];
        #pragma unroll
        for (int k = 1; k < VPT; k++) m = max(m, v[k]);
        #pragma unroll
        for (int o = 16; o > 0; o >>= 1) m = max(m, __shfl_xor_sync(0xFFFFFFFFu, m, o));
        if (lane == 0) s_max[warp] = m;
        __syncthreads();                     // barrier 1
        int xmax = s_max[0];
        #pragma unroll
        for (int w = 1; w < NWARP; w++) xmax = max(xmax, s_max[w]);

        // ---- gather exp_q + exact int sum ----
        int e[VPT];
        int sum = 0;
        #pragma unroll
        for (int k = 0; k < VPT; k++) {
            int idx = v[k] - xmax + 255;
            idx = min(max(idx, 0), 255);
            e[k] = s_tab[(idx << 5) + lane];
            sum += e[k];
        }

        #pragma unroll
        for (int o = 16; o > 0; o >>= 1) sum += __shfl_xor_sync(0xFFFFFFFFu, sum, o);
        if (lane == 0) s_sum[warp] = sum;
        __syncthreads();                     // barrier 2
        int total = s_sum[0];
        #pragma unroll
        for (int w = 1; w < NWARP; w++) total += s_sum[w];

        const float inv = 1.0f / (float)total;

        float4 o0, o1;
        o0.x = (float)e[0] * inv; o0.y = (float)e[1] * inv;
        o0.z = (float)e[2] * inv; o0.w = (float)e[3] * inv;
        o1.x = (float)e[4] * inv; o1.y = (float)e[5] * inv;
        o1.z = (float)e[6] * inv; o1.w = (float)e[7] * inv;
        float4* op = reinterpret_cast<float4*>(out + row * ROW) + tid * 2;
        op[0] = o0;
        op[1] = o1;
    }
}

extern "C" void kernel_launch(void* const* d_in, const int* in_sizes, int n_in,
                              void* d_out, int out_size) {
    const int* x             = (const int*)d_in[0];
    const float* input_scale = (const float*)d_in[1];
    const float* exp_scale   = (const float*)d_in[2];
    float* out = (float*)d_out;

    const int n_rows = in_sizes[0] / ROW;

    int nblocks = 152 * 6;                   // 6 CTAs/SM (smem-limited), full GB300
    if (nblocks > n_rows) nblocks = n_rows;

    build_table_kernel<<<1, 256>>>(input_scale, exp_scale);
    softmax_bernoulli2_kernel<<<nblocks, TPB>>>(x, out, n_rows);
}

// round 3
// speedup vs baseline: 1.6666x; 1.0040x over previous
#include <cuda_runtime.h>
#include <cuda_bf16.h>
#include <math.h>

// Quantized softmax (SoftmaxBernoulli2): rows of 2048 int32 in [-128,127].
// LUT[q] = clip(round(exp((q-255)*is)/es),0,255); idx = x - rowmax + 255 (always in [0,255]);
// out = LUT[idx] / sum_row(LUT[idx]) as fp32.
//
// R3: uchar4-packed replicated LUT (8KB smem, conflict-free: word=(idx>>2), bank=lane,
// byte via PRMT), bytewise-packed inputs + __vmaxu4 reductions, <=32 regs ->
// 8 CTAs/SM (100% occupancy). Persistent grid-stride with cross-row prefetch.

#define ROW   2048
#define TPB   256
#define NWARP (TPB / 32)

__device__ unsigned g_ptab[64];   // table packed 4 entries/word, entries in [0,255]

__global__ void build_table_kernel(const float* __restrict__ input_scale,
                                   const float* __restrict__ exp_scale) {
    // one warp builds 64 packed words; thread j packs entries 4j..4j+3
    int j = threadIdx.x;
    if (j < 64) {
        double is = (double)input_scale[0];
        double es = (double)exp_scale[0];
        unsigned w = 0;
        #pragma unroll
        for (int b = 0; b < 4; b++) {
            int q = 4 * j + b;                       // 0..255 -> quant value q-255
            double r = nearbyint(exp((double)(q - 255) * is) / es);  // half-even
            r = fmin(fmax(r, 0.0), 255.0);
            w |= ((unsigned)(int)r) << (8 * b);
        }
        g_ptab[j] = w;
    }
}

__global__ __launch_bounds__(TPB, 8) void softmax_bernoulli2_kernel(
    const int* __restrict__ x, float* __restrict__ out, int n_rows) {
    // Replicated packed LUT: s_tab[word*32 + lane] -> bank == lane, conflict-free.
    __shared__ unsigned s_tab[64 * 32];
    __shared__ int s_max[NWARP];
    __shared__ int s_sum[NWARP];

    const int tid  = threadIdx.x;
    const int lane = tid & 31;
    const int warp = tid >> 5;

    // One-time fill (8 iterations): broadcast LDG, conflict-free STS.
    #pragma unroll
    for (int i = tid; i < 64 * 32; i += TPB) {
        s_tab[i] = g_ptab[i >> 5];
    }
    __syncthreads();

    const long long stride = gridDim.x;
    long long row = blockIdx.x;
    if (row >= n_rows) return;

    // Prefetch first row: thread t owns elements [t*8, t*8+8), two int4 (coalesced).
    int4 a = *(reinterpret_cast<const int4*>(x + row * ROW) + tid * 2);
    int4 b = *(reinterpret_cast<const int4*>(x + row * ROW) + tid * 2 + 1);

    for (; row < n_rows; row += stride) {
        // Pack u = v + 128 (in [0,255]) bytewise: pv0 = elems 0..3, pv1 = elems 4..7.
        unsigned u0 = (unsigned)(a.x + 128), u1 = (unsigned)(a.y + 128);
        unsigned u2 = (unsigned)(a.z + 128), u3 = (unsigned)(a.w + 128);
        unsigned u4 = (unsigned)(b.x + 128), u5 = (unsigned)(b.y + 128);
        unsigned u6 = (unsigned)(b.z + 128), u7 = (unsigned)(b.w + 128);
        unsigned pv0 = __byte_perm(__byte_perm(u0, u1, 0x0040),
                                   __byte_perm(u2, u3, 0x0040), 0x5410);
        unsigned pv1 = __byte_perm(__byte_perm(u4, u5, 0x0040),
                                   __byte_perm(u6, u7, 0x0040), 0x5410);

        // Issue next row's loads NOW so they fly during the reductions.
        long long nrow = row + stride;
        if (nrow < n_rows) {
            const int4* np = reinterpret_cast<const int4*>(x + nrow * ROW) + tid * 2;
            a = np[0];
            b = np[1];
        }

        // ---- block max in packed u-space ----
        unsigned pm = __vmaxu4(pv0, pv1);
        #pragma unroll
        for (int o = 16; o > 0; o >>= 1)
            pm = __vmaxu4(pm, __shfl_xor_sync(0xFFFFFFFFu, pm, o));
        pm = __vmaxu4(pm, pm >> 16);
        pm = __vmaxu4(pm, pm >> 8);
        if (lane == 0) s_max[warp] = (int)(pm & 255u);
        __syncthreads();                       // barrier 1
        int t = s_max[0];
        #pragma unroll
        for (int w = 1; w < NWARP; w++) t = max(t, s_max[w]);
        const unsigned c = 255u - (unsigned)t; // idx = u + c, guaranteed in [0,255]
        const unsigned laneB = (unsigned)lane;

        // ---- gather exp_q from packed LUT + exact int sum ----
        int e[8];
        int sum = 0;
        #pragma unroll
        for (int k = 0; k < 8; k++) {
            unsigned u = __byte_perm(k < 4 ? pv0 : pv1, 0, 0x4440u | (k & 3));
            unsigned idx = u + c;
            unsigned w = s_tab[((idx >> 2) << 5) + laneB];
            e[k] = (int)__byte_perm(w, 0, 0x4440u | (idx & 3u));
            sum += e[k];
        }

        #pragma unroll
        for (int o = 16; o > 0; o >>= 1) sum += __shfl_xor_sync(0xFFFFFFFFu, sum, o);
        if (lane == 0) s_sum[warp] = sum;
        __syncthreads();                       // barrier 2
        int total = s_sum[0];
        #pragma unroll
        for (int w = 1; w < NWARP; w++) total += s_sum[w];

        const float inv = 1.0f / (float)total;

        float4 o0, o1;
        o0.x = (float)e[0] * inv; o0.y = (float)e[1] * inv;
        o0.z = (float)e[2] * inv; o0.w = (float)e[3] * inv;
        o1.x = (float)e[4] * inv; o1.y = (float)e[5] * inv;
        o1.z = (float)e[6] * inv; o1.w = (float)e[7] * inv;
        float4* op = reinterpret_cast<float4*>(out + row * ROW) + tid * 2;
        op[0] = o0;
        op[1] = o1;
    }
}

extern "C" void kernel_launch(void* const* d_in, const int* in_sizes, int n_in,
                              void* d_out, int out_size) {
    const int* x             = (const int*)d_in[0];
    const float* input_scale = (const float*)d_in[1];
    const float* exp_scale   = (const float*)d_in[2];
    float* out = (float*)d_out;

    const int n_rows = in_sizes[0] / ROW;

    int nblocks = 152 * 8;                     // 8 CTAs/SM (8KB smem, <=32 regs)
    if (nblocks > n_rows) nblocks = n_rows;

    build_table_kernel<<<1, 64>>>(input_scale, exp_scale);
    softmax_bernoulli2_kernel<<<nblocks, TPB>>>(x, out, n_rows);
}